// round 11
// baseline (speedup 1.0000x reference)
#include <cuda_runtime.h>

#define T_LEN 512
#define B_SZ  512
#define I_SZ  100
#define H_SZ  96
#define G3    288   // 3*H
#define BCH   7     // batch rows per scan block (74 chunks x 2 dirs = 148 blocks)
#define NCHUNK 74
#define PROJ_T 384   // 96 jj x 4 k-quarters
#define SCAN_T 384   // 96 j  x 4 k-quarters
#define HPAD  100    // padded h row (bank-conflict-free duty stores)

typedef unsigned long long u64;

// Scratch: input projections for both directions: [2][T][B][3H] fp32
static __device__ float g_xproj[2ull * T_LEN * B_SZ * G3];

// ---- packed fp32x2 helpers (sm_103a FFMA2 path; bit-identical to 2x fmaf) ----
__device__ __forceinline__ u64 ffma2(u64 a, u64 b, u64 c) {
    u64 d;
    asm("fma.rn.f32x2 %0, %1, %2, %3;" : "=l"(d) : "l"(a), "l"(b), "l"(c));
    return d;
}
__device__ __forceinline__ u64 pack2(float lo, float hi) {
    u64 p;
    asm("mov.b64 %0, {%1, %2};" : "=l"(p) : "f"(lo), "f"(hi));
    return p;
}
__device__ __forceinline__ float hsum2(u64 p) {
    float lo, hi;
    asm("mov.b64 {%0, %1}, %2;" : "=f"(lo), "=f"(hi) : "l"(p));
    return lo + hi;
}
// combine the 4 k-quarter partials held by lanes l, l^8, l^16, l^24
__device__ __forceinline__ float qreduce(float v) {
    v += __shfl_xor_sync(0xffffffffu, v, 8);
    v += __shfl_xor_sync(0xffffffffu, v, 16);
    return v;
}

__device__ __forceinline__ float fast_sigmoid(float x) {
    float e, r;
    asm("ex2.approx.f32 %0, %1;" : "=f"(e) : "f"(-1.4426950408889634f * x));
    asm("rcp.approx.f32 %0, %1;" : "=f"(r) : "f"(1.0f + e));
    return r;
}
__device__ __forceinline__ float fast_tanh(float x) {
    float e, r;
    asm("ex2.approx.f32 %0, %1;" : "=f"(e) : "f"(-2.8853900817779268f * x));
    asm("rcp.approx.f32 %0, %1;" : "=f"(r) : "f"(1.0f + e));
    return 2.0f * r - 1.0f;
}

// ---------------------------------------------------------------------------
// Projection v4 (warp-autonomous, barrier-free):
// 384 threads: thread = (jj, q); jj = warp*8 + (lane&7) in [0,96),
// q = lane>>3 = k-quarter. Owns gate rows jj, jj+96, jj+192.
// k split 24/24/24/28 floats at offsets {0,24,48,72} (16B-aligned);
// quarters 0-2 zero-pad weights to 28. x read directly GMEM->L1 (no smem,
// no __syncthreads). Duty lane q == (row&3) stores the 3 results.
// ---------------------------------------------------------------------------
__global__ __launch_bounds__(PROJ_T, 1) void proj_kernel(
    const float* __restrict__ x,
    const float* __restrict__ w_ih_f, const float* __restrict__ b_ih_f,
    const float* __restrict__ w_ih_b, const float* __restrict__ b_ih_b)
{
    const int dir    = blockIdx.x & 1;
    const int chunk  = blockIdx.x >> 1;
    const int nchunk = gridDim.x >> 1;
    const long R = (long)T_LEN * B_SZ;
    const long rows_per = (R + nchunk - 1) / nchunk;
    const long r0 = (long)chunk * rows_per;
    const long r1 = (r0 + rows_per < R) ? (r0 + rows_per) : R;

    const float* w    = dir ? w_ih_b : w_ih_f;
    const float* bias = dir ? b_ih_b : b_ih_f;
    float* xp = g_xproj + (size_t)dir * T_LEN * B_SZ * G3;

    const int t    = threadIdx.x;
    const int lane = t & 31;
    const int q    = lane >> 3;                 // k-quarter
    const int jj   = (t >> 5) * 8 + (lane & 7); // 0..95

    // weights: rows jj, jj+96, jj+192; k floats [24q, 24q+28) = 14 u64.
    // byte offset g*400 + 96q is 16B-aligned; quarters 0-2 zero the pad.
    u64 wr[3][14];
    #pragma unroll
    for (int r = 0; r < 3; r++) {
        const u64* p = (const u64*)(w + (jj + 96 * r) * I_SZ + 24 * q);
        #pragma unroll
        for (int k = 0; k < 14; k++) wr[r][k] = p[k];
        if (q < 3) { wr[r][12] = 0ull; wr[r][13] = 0ull; }
    }
    float bg[3];
    #pragma unroll
    for (int r = 0; r < 3; r++) bg[r] = q ? 0.0f : bias[jj + 96 * r];

    // row loop: all warps walk the same rows (L1 broadcast), no sync anywhere
    #pragma unroll 2
    for (long row = r0; row < r1; ++row) {
        // 7 LDG.128 of this row's k-quarter window [24q, 24q+28)
        const ulonglong2* xa = (const ulonglong2*)(x + row * I_SZ) + q * 6;
        ulonglong2 xv[7];
        #pragma unroll
        for (int kk = 0; kk < 7; kk++) xv[kk] = xa[kk];

        u64 acc[3];
        #pragma unroll
        for (int r = 0; r < 3; r++) acc[r] = pack2(bg[r], 0.0f);
        #pragma unroll
        for (int kk = 0; kk < 7; kk++) {
            #pragma unroll
            for (int r = 0; r < 3; r++) {
                acc[r] = ffma2(xv[kk].x, wr[r][2 * kk],     acc[r]);
                acc[r] = ffma2(xv[kk].y, wr[r][2 * kk + 1], acc[r]);
            }
        }

        // combine k-quarters; duty lane (q == row&3) stores 3 results
        float s0 = qreduce(hsum2(acc[0]));
        float s1 = qreduce(hsum2(acc[1]));
        float s2 = qreduce(hsum2(acc[2]));
        if (q == (int)(row & 3)) {
            float* o = xp + row * G3 + jj;
            o[0]   = s0;
            o[96]  = s1;
            o[192] = s2;
        }
    }
}

// ---------------------------------------------------------------------------
// Scan (R10 winner, unchanged): 384 threads, thread = (j, q), owns gate rows
// j, j+96, j+192; duty lanes compute gates in registers; h double-buffered
// in smem; ONE __syncthreads per step.
// ---------------------------------------------------------------------------
__global__ __launch_bounds__(SCAN_T, 1) void scan_kernel(
    const float* __restrict__ w_hh_f, const float* __restrict__ b_hh_f,
    const float* __restrict__ w_hh_b, const float* __restrict__ b_hh_b,
    float* __restrict__ out)
{
    const int dir = blockIdx.y;
    const int b0  = blockIdx.x * BCH;
    const float* w    = dir ? w_hh_b : w_hh_f;
    const float* bias = dir ? b_hh_b : b_hh_f;
    const float* xp = g_xproj + (size_t)dir * T_LEN * B_SZ * G3;

    const int t    = threadIdx.x;
    const int lane = t & 31;
    const int q    = lane >> 3;
    const int j    = (t >> 5) * 8 + (lane & 7);   // 0..95

    // weights: rows j, j+96, j+192; k in [24q, 24q+24): 12 u64 each
    u64 wr[3][12];
    #pragma unroll
    for (int r = 0; r < 3; r++) {
        const u64* p = (const u64*)(w + (j + 96 * r) * H_SZ + 24 * q);
        #pragma unroll
        for (int k = 0; k < 12; k++) wr[r][k] = p[k];
    }
    float bg[3];
    #pragma unroll
    for (int r = 0; r < 3; r++) bg[r] = q ? 0.0f : bias[j + 96 * r];

    // double-buffered hidden state, rows padded to HPAD floats
    __shared__ __align__(16) float h_s[2][BCH][HPAD];
    for (int idx = t; idx < 2 * BCH * HPAD; idx += SCAN_T) ((float*)h_s)[idx] = 0.0f;

    // duty batches for this lane: b = q and q+4
    const int bd0 = q;
    const int bd1 = q + 4;               // valid iff < BCH
    const bool d1v = (bd1 < BCH);
    int row0 = b0 + bd0; if (row0 > B_SZ - 1) row0 = B_SZ - 1;
    int row1 = b0 + (d1v ? bd1 : 0); if (row1 > B_SZ - 1) row1 = B_SZ - 1;
    const bool w0v = (b0 + bd0 < B_SZ);
    const bool w1v = d1v && (b0 + bd1 < B_SZ);

    float hold0 = 0.0f, hold1 = 0.0f;    // this lane's h[b][j], prev step

    // prime xq for step 0 (duty lanes)
    float xq0[3], xq1[3];
    {
        const int t0 = dir ? (T_LEN - 1) : 0;
        const float* p0 = xp + ((size_t)t0 * B_SZ + row0) * G3 + j;
        const float* p1 = xp + ((size_t)t0 * B_SZ + row1) * G3 + j;
        #pragma unroll
        for (int r = 0; r < 3; r++) {
            xq0[r] = p0[96 * r];
            xq1[r] = d1v ? p1[96 * r] : 0.0f;
        }
    }
    __syncthreads();

    int p = 0;
    for (int it = 0; it < T_LEN; it++) {
        const int tc = dir ? (T_LEN - 1 - it) : it;

        // prefetch next step's xq (DRAM latency hidden under this step)
        float xn0[3], xn1[3];
        #pragma unroll
        for (int r = 0; r < 3; r++) { xn0[r] = 0.0f; xn1[r] = 0.0f; }
        if (it + 1 < T_LEN) {
            const int tn = dir ? (T_LEN - 2 - it) : (it + 1);
            const float* p0 = xp + ((size_t)tn * B_SZ + row0) * G3 + j;
            const float* p1 = xp + ((size_t)tn * B_SZ + row1) * G3 + j;
            #pragma unroll
            for (int r = 0; r < 3; r++) {
                xn0[r] = p0[96 * r];
                xn1[r] = d1v ? p1[96 * r] : 0.0f;
            }
        }

        // partial hp for 3 rows x BCH batches, this thread's k-quarter
        u64 acc[3][BCH];
        #pragma unroll
        for (int r = 0; r < 3; r++)
            #pragma unroll
            for (int b = 0; b < BCH; b++) acc[r][b] = pack2(bg[r], 0.0f);

        const ulonglong2* h2 = (const ulonglong2*)h_s[p] + q * 6;  // row = 25 u2
        #pragma unroll
        for (int kk = 0; kk < 6; kk++) {
            #pragma unroll
            for (int b = 0; b < BCH; b++) {
                ulonglong2 hv = h2[b * (HPAD / 4) + kk];
                #pragma unroll
                for (int r = 0; r < 3; r++) {
                    acc[r][b] = ffma2(hv.x, wr[r][2 * kk],     acc[r][b]);
                    acc[r][b] = ffma2(hv.y, wr[r][2 * kk + 1], acc[r][b]);
                }
            }
        }

        // reduce quartets; keep only this lane's duty batches (less reg pressure)
        float v0d[3], v1d[3];
        #pragma unroll
        for (int r = 0; r < 3; r++) {
            #pragma unroll
            for (int b = 0; b < BCH; b++) {
                const float vv = qreduce(hsum2(acc[r][b]));
                if (b == bd0) v0d[r] = vv;
                if (d1v && b == bd1) v1d[r] = vv;
            }
        }

        // duty lane computes gates fully in registers, writes new h
        {
            const float rg = fast_sigmoid(v0d[0] + xq0[0]);
            const float zg = fast_sigmoid(v0d[1] + xq0[1]);
            const float ng = fast_tanh(fmaf(rg, v0d[2], xq0[2]));
            const float hn = fmaf(zg, hold0 - ng, ng);
            hold0 = hn;
            h_s[p ^ 1][bd0][j] = hn;
            if (w0v)
                out[((size_t)tc * B_SZ + (b0 + bd0)) * (2 * H_SZ) + dir * H_SZ + j] = hn;
        }
        if (d1v) {
            const float rg = fast_sigmoid(v1d[0] + xq1[0]);
            const float zg = fast_sigmoid(v1d[1] + xq1[1]);
            const float ng = fast_tanh(fmaf(rg, v1d[2], xq1[2]));
            const float hn = fmaf(zg, hold1 - ng, ng);
            hold1 = hn;
            h_s[p ^ 1][bd1][j] = hn;
            if (w1v)
                out[((size_t)tc * B_SZ + (b0 + bd1)) * (2 * H_SZ) + dir * H_SZ + j] = hn;
        }

        #pragma unroll
        for (int r = 0; r < 3; r++) { xq0[r] = xn0[r]; xq1[r] = xn1[r]; }

        __syncthreads();
        p ^= 1;
    }
}

extern "C" void kernel_launch(void* const* d_in, const int* in_sizes, int n_in,
                              void* d_out, int out_size) {
    const float* x    = (const float*)d_in[0];
    const float* wihf = (const float*)d_in[1];
    const float* whhf = (const float*)d_in[2];
    const float* bihf = (const float*)d_in[3];
    const float* bhhf = (const float*)d_in[4];
    const float* wihb = (const float*)d_in[5];
    const float* whhb = (const float*)d_in[6];
    const float* bihb = (const float*)d_in[7];
    const float* bhhb = (const float*)d_in[8];
    float* out = (float*)d_out;

    proj_kernel<<<148, PROJ_T>>>(x, wihf, bihf, wihb, bihb);
    dim3 sg(NCHUNK, 2);
    scan_kernel<<<sg, SCAN_T>>>(whhf, bhhf, whhb, bhhb, out);
}